// round 1
// baseline (speedup 1.0000x reference)
#include <cuda_runtime.h>

// Problem constants (fixed shapes from the reference)
#define B_SZ   2048
#define IN_F   1024
#define N_C    64
#define E_SZ   128
#define O_SZ   256          // 2*E
#define TM     128          // rows (batch) per CTA
#define TK     16           // K tile
#define SLOPE  0.01f

// 128x256 output tile per CTA, 512 threads, each thread computes 8x8.
// Thread (ty, tx): rows ty*8..+7, cols tx*8..+7.  tx = lane id -> the 32
// lanes of a warp cover one row-group's full 256 columns, so the gate dot
// product reduces with warp shuffles and the pos/neg halves pair via
// shfl_down(.,16).
__global__ __launch_bounds__(512, 1)
void concept_fused_kernel(const float* __restrict__ x,
                          const float* __restrict__ Wc,
                          const float* __restrict__ bc,
                          const float* __restrict__ wp,
                          const float* __restrict__ bp,
                          float* __restrict__ out)
{
    __shared__ float Xs[2][TM][TK];     // 16 KB
    __shared__ float Ws[2][TK][O_SZ];   // 32 KB  (total = 48 KB exactly)

    const int tid = threadIdx.x;        // 0..511
    const int tx  = tid & 31;           // lane / col group
    const int ty  = tid >> 5;           // warp / row group (0..15)
    const int n   = blockIdx.y;         // concept
    const int m0  = blockIdx.x * TM;    // batch-row base

    const float* Wn = Wc + (size_t)n * IN_F * O_SZ;

    // --- load-index precompute ---
    // X tile: 128 rows x 16 k = 512 float4, one per thread
    const int xr = tid >> 2;                 // 0..127
    const int xc = (tid & 3) << 2;           // 0,4,8,12
    // W tile: 16 k x 256 = 1024 float4, two per thread
    const int wk0 = tid >> 6;                // 0..7 (and +8 for second)
    const int wo0 = (tid & 63) << 2;         // 0..252

    float4 xreg, wreg0, wreg1;

    // prologue: load tile 0 into buffer 0
    xreg  = *reinterpret_cast<const float4*>(x + (size_t)(m0 + xr) * IN_F + xc);
    wreg0 = *reinterpret_cast<const float4*>(Wn + (size_t)wk0       * O_SZ + wo0);
    wreg1 = *reinterpret_cast<const float4*>(Wn + (size_t)(wk0 + 8) * O_SZ + wo0);
    *reinterpret_cast<float4*>(&Xs[0][xr][xc])      = xreg;
    *reinterpret_cast<float4*>(&Ws[0][wk0][wo0])     = wreg0;
    *reinterpret_cast<float4*>(&Ws[0][wk0 + 8][wo0]) = wreg1;
    __syncthreads();

    float acc[8][8];
#pragma unroll
    for (int i = 0; i < 8; ++i)
#pragma unroll
        for (int j = 0; j < 8; ++j) acc[i][j] = 0.f;

    const int NT = IN_F / TK;   // 64 K-iterations
    for (int t = 0; t < NT; ++t) {
        const int cur = t & 1;
        const int nxt = cur ^ 1;

        // prefetch next tile into registers (overlaps with compute)
        if (t + 1 < NT) {
            const int k0 = (t + 1) * TK;
            xreg  = *reinterpret_cast<const float4*>(x + (size_t)(m0 + xr) * IN_F + k0 + xc);
            wreg0 = *reinterpret_cast<const float4*>(Wn + (size_t)(k0 + wk0)     * O_SZ + wo0);
            wreg1 = *reinterpret_cast<const float4*>(Wn + (size_t)(k0 + wk0 + 8) * O_SZ + wo0);
        }

#pragma unroll
        for (int kk = 0; kk < TK; ++kk) {
            float a[8];
#pragma unroll
            for (int i = 0; i < 8; ++i) a[i] = Xs[cur][ty * 8 + i][kk];  // warp broadcast
            const float4 b0 = *reinterpret_cast<const float4*>(&Ws[cur][kk][tx * 8]);
            const float4 b1 = *reinterpret_cast<const float4*>(&Ws[cur][kk][tx * 8 + 4]);
            const float b[8] = {b0.x, b0.y, b0.z, b0.w, b1.x, b1.y, b1.z, b1.w};
#pragma unroll
            for (int i = 0; i < 8; ++i)
#pragma unroll
                for (int j = 0; j < 8; ++j)
                    acc[i][j] = fmaf(a[i], b[j], acc[i][j]);
        }

        // stage next tile; the trailing sync also protects the buffer we'll
        // overwrite two iterations from now
        if (t + 1 < NT) {
            *reinterpret_cast<float4*>(&Xs[nxt][xr][xc])      = xreg;
            *reinterpret_cast<float4*>(&Ws[nxt][wk0][wo0])     = wreg0;
            *reinterpret_cast<float4*>(&Ws[nxt][wk0 + 8][wo0]) = wreg1;
        }
        __syncthreads();
    }

    // ---------------- fused epilogue ----------------
    // bias + LeakyReLU, gate dot (warp-reduced), sigmoid, pos/neg blend.
    const float bprob = *bp;
    const float* bcn  = bc + (size_t)n * O_SZ;

#pragma unroll
    for (int i = 0; i < 8; ++i) {
        float dot = 0.f;
#pragma unroll
        for (int j = 0; j < 8; ++j) {
            const int c = tx * 8 + j;
            float v = acc[i][j] + bcn[c];
            v = (v >= 0.f) ? v : SLOPE * v;
            acc[i][j] = v;
            dot = fmaf(v, wp[c], dot);
        }
        // full-warp reduction over the 256 columns (all lanes share this row)
#pragma unroll
        for (int off = 16; off > 0; off >>= 1)
            dot += __shfl_xor_sync(0xffffffffu, dot, off);

        const float pr = 1.f / (1.f + expf(-(dot + bprob)));
        const int r = m0 + ty * 8 + i;

        // lane tx (<16) holds ctx[e], lane tx+16 holds ctx[e+128], same e range
        float e[8];
#pragma unroll
        for (int j = 0; j < 8; ++j) {
            const float neg = __shfl_down_sync(0xffffffffu, acc[i][j], 16);
            e[j] = fmaf(acc[i][j] - neg, pr, neg);   // pos*p + neg*(1-p)
        }
        if (tx < 16) {
            float* op = out + ((size_t)r * N_C + n) * E_SZ + tx * 8;
            *reinterpret_cast<float4*>(op)     = make_float4(e[0], e[1], e[2], e[3]);
            *reinterpret_cast<float4*>(op + 4) = make_float4(e[4], e[5], e[6], e[7]);
        }
        if (tx == 0) {
            out[(size_t)B_SZ * N_C * E_SZ + (size_t)r * N_C + n] = pr;
        }
    }
}

extern "C" void kernel_launch(void* const* d_in, const int* in_sizes, int n_in,
                              void* d_out, int out_size)
{
    const float* x  = (const float*)d_in[0];   // [2048,1024]
    const float* Wc = (const float*)d_in[1];   // [64,1024,256]
    const float* bc = (const float*)d_in[2];   // [64,256]
    const float* wp = (const float*)d_in[3];   // [256]
    const float* bp = (const float*)d_in[4];   // scalar
    float* out = (float*)d_out;                // c_emb [2048,64,128] then c_pred [2048,64]

    dim3 grid(B_SZ / TM, N_C);
    concept_fused_kernel<<<grid, 512>>>(x, Wc, bc, wp, bp, out);
}

// round 3
// speedup vs baseline: 3.5255x; 3.5255x over previous
#include <cuda_runtime.h>
#include <cstdint>

// ---------------- problem constants ----------------
#define B_SZ   2048
#define IN_F   1024
#define N_C    64
#define E_SZ   128
#define O_SZ   256
#define TM     128
#define KT     32
#define NCHUNK (IN_F / KT)   // 32
#define SLOPE  0.01f
#define LDA    36            // padded smem row (floats) -> conflict-free LDS.128
#define LDB    36

// ---------------- scratch (static device globals) ----------------
__device__ float g_Xt[B_SZ * IN_F];                     // tf32-rounded, k-permuted
__device__ float g_Wt[(size_t)N_C * O_SZ * IN_F];       // [n][o][k] tf32, k-permuted

// ---------------- helpers ----------------
__device__ __forceinline__ uint32_t smem_u32(const void* p) {
    uint32_t a;
    asm("{ .reg .u64 t; cvta.to.shared.u64 t, %1; cvt.u32.u64 %0, t; }" : "=r"(a) : "l"(p));
    return a;
}
__device__ __forceinline__ float to_tf32(float x) {
    uint32_t u; asm("cvt.rna.tf32.f32 %0, %1;" : "=r"(u) : "f"(x));
    return __uint_as_float(u);
}
__device__ __forceinline__ void cp16(uint32_t dst, const void* src) {
    asm volatile("cp.async.cg.shared.global [%0], [%1], 16;" :: "r"(dst), "l"(src) : "memory");
}
__device__ __forceinline__ void lds4(uint32_t addr, uint32_t& x, uint32_t& y,
                                     uint32_t& z, uint32_t& w) {
    asm volatile("ld.shared.v4.b32 {%0,%1,%2,%3}, [%4];"
                 : "=r"(x), "=r"(y), "=r"(z), "=r"(w) : "r"(addr));
}
__device__ __forceinline__ void mma_tf32(float* d, uint32_t a0, uint32_t a1,
                                         uint32_t a2, uint32_t a3,
                                         uint32_t b0, uint32_t b1) {
    asm volatile(
        "mma.sync.aligned.m16n8k8.row.col.f32.tf32.tf32.f32 "
        "{%0,%1,%2,%3}, {%4,%5,%6,%7}, {%8,%9}, {%0,%1,%2,%3};"
        : "+f"(d[0]), "+f"(d[1]), "+f"(d[2]), "+f"(d[3])
        : "r"(a0), "r"(a1), "r"(a2), "r"(a3), "r"(b0), "r"(b1));
}

// ---------------- converters ----------------
// k-permutation within each aligned 32-block: position p holds k = (p>>3) + 4*(p&7).
// Thread fragments then read 8 contiguous floats at offset (lane&3)*8.

__global__ void conv_x(const float* __restrict__ x) {
    const int c = blockIdx.x * blockDim.x + threadIdx.x;   // 32-float chunk id
    const float4* src = reinterpret_cast<const float4*>(x) + (size_t)c * 8;
    float v[32];
#pragma unroll
    for (int f = 0; f < 8; ++f) {
        float4 t = src[f];
        v[4*f] = t.x; v[4*f+1] = t.y; v[4*f+2] = t.z; v[4*f+3] = t.w;
    }
    float o[32];
#pragma unroll
    for (int p = 0; p < 32; ++p) o[p] = to_tf32(v[(p >> 3) + 4 * (p & 7)]);
    float4* dst = reinterpret_cast<float4*>(g_Xt) + (size_t)c * 8;
#pragma unroll
    for (int f = 0; f < 8; ++f) dst[f] = make_float4(o[4*f], o[4*f+1], o[4*f+2], o[4*f+3]);
}

// W[n][k][o] -> g_Wt[n][o][kperm]
__global__ void conv_w(const float* __restrict__ W) {
    __shared__ float tile[32][33];
    const int n = blockIdx.z, k0 = blockIdx.x * 32, o0 = blockIdx.y * 32;
    const int tx = threadIdx.x, ty = threadIdx.y;   // 32 x 8
    const float* src = W + ((size_t)n * IN_F + k0) * O_SZ + o0;
#pragma unroll
    for (int i = 0; i < 4; ++i)
        tile[ty + 8*i][tx] = src[(size_t)(ty + 8*i) * O_SZ + tx];
    __syncthreads();
    const int kp = k0 + (tx & 3) * 8 + (tx >> 2);   // permuted position for k=tx
    const size_t base = (size_t)n * O_SZ + o0;
#pragma unroll
    for (int i = 0; i < 4; ++i) {
        const int o = ty + 8*i;
        g_Wt[(base + o) * IN_F + kp] = to_tf32(tile[tx][o]);
    }
}

// ---------------- GEMM + fused epilogue ----------------
// dyn smem: [0, 2*55296): double buffer { A 128x36 (18432B), B 256x36 (36864B) }
//           epilogue overlay: nctx[128][132] floats at 0 (67584B)
//           sdot[128][8] at 110592, pv[128] at 114688
#define BUF_BYTES  55296
#define B_OFF      18432
#define SD_OFF     110592
#define PV_OFF     114688
#define SMEM_TOTAL 115200

__global__ __launch_bounds__(512, 1)
void concept_mma_kernel(const float* __restrict__ bc,
                        const float* __restrict__ wp,
                        const float* __restrict__ bp,
                        float* __restrict__ out)
{
    extern __shared__ char smem[];
    const uint32_t sb = smem_u32(smem);
    const int tid = threadIdx.x, lane = tid & 31, wid = tid >> 5;
    const int wn = wid & 7, wm = wid >> 3;     // 8 N-warps x 2 M-warps
    const int n = blockIdx.y, m0 = blockIdx.x * TM;

    const float* Ag = g_Xt + (size_t)m0 * IN_F;
    const float* Bg = g_Wt + (size_t)n * O_SZ * IN_F;

    float acc[4][4][4];
#pragma unroll
    for (int a = 0; a < 4; ++a)
#pragma unroll
        for (int b = 0; b < 4; ++b)
#pragma unroll
            for (int c = 0; c < 4; ++c) acc[a][b][c] = 0.f;

    // A-tile copy: 1024 x 16B, 2/thread.  B-tile: 2048 x 16B, 4/thread.
    const int arow = tid >> 3, aseg = tid & 7;           // + 512*j -> row += 64
    // ---- prologue: chunk 0 ----
    {
        const uint32_t ab = sb, bb = sb + B_OFF;
#pragma unroll
        for (int j = 0; j < 2; ++j)
            cp16(ab + ((arow + 64*j) * LDA + aseg * 4) * 4,
                 Ag + (size_t)(arow + 64*j) * IN_F + aseg * 4);
#pragma unroll
        for (int j = 0; j < 4; ++j)
            cp16(bb + ((arow + 64*j) * LDB + aseg * 4) * 4,
                 Bg + (size_t)(arow + 64*j) * IN_F + aseg * 4);
        asm volatile("cp.async.commit_group;" ::: "memory");
        asm volatile("cp.async.wait_group 0;" ::: "memory");
        __syncthreads();
    }

    for (int t = 0; t < NCHUNK; ++t) {
        if (t + 1 < NCHUNK) {   // prefetch next chunk into other buffer
            const uint32_t ab = sb + ((t + 1) & 1) * BUF_BYTES, bb = ab + B_OFF;
            const float* An = Ag + (t + 1) * KT;
            const float* Bn = Bg + (t + 1) * KT;
#pragma unroll
            for (int j = 0; j < 2; ++j)
                cp16(ab + ((arow + 64*j) * LDA + aseg * 4) * 4,
                     An + (size_t)(arow + 64*j) * IN_F + aseg * 4);
#pragma unroll
            for (int j = 0; j < 4; ++j)
                cp16(bb + ((arow + 64*j) * LDB + aseg * 4) * 4,
                     Bn + (size_t)(arow + 64*j) * IN_F + aseg * 4);
            asm volatile("cp.async.commit_group;" ::: "memory");
        }

        const uint32_t ab = sb + (t & 1) * BUF_BYTES, bb = ab + B_OFF;
#pragma unroll
        for (int h = 0; h < 2; ++h) {                    // k8 steps {2h, 2h+1}
            uint32_t bf[4][4];
#pragma unroll
            for (int nt = 0; nt < 4; ++nt) {
                const int nrow = wn * 32 + nt * 8 + (lane >> 2);
                lds4(bb + (nrow * LDB + (lane & 3) * 8 + h * 4) * 4,
                     bf[nt][0], bf[nt][1], bf[nt][2], bf[nt][3]);
            }
#pragma unroll
            for (int mt = 0; mt < 4; ++mt) {
                const int r0 = wm * 64 + mt * 16 + (lane >> 2);
                uint32_t a0[4], a1[4];
                lds4(ab + (r0 * LDA + (lane & 3) * 8 + h * 4) * 4,
                     a0[0], a0[1], a0[2], a0[3]);
                lds4(ab + ((r0 + 8) * LDA + (lane & 3) * 8 + h * 4) * 4,
                     a1[0], a1[1], a1[2], a1[3]);
#pragma unroll
                for (int g = 0; g < 2; ++g) {
#pragma unroll
                    for (int nt = 0; nt < 4; ++nt)
                        mma_tf32(acc[mt][nt],
                                 a0[2*g], a1[2*g], a0[2*g+1], a1[2*g+1],
                                 bf[nt][2*g], bf[nt][2*g+1]);
                }
            }
        }
        asm volatile("cp.async.wait_group 0;" ::: "memory");
        __syncthreads();
    }

    // ---------------- fused epilogue ----------------
    const float* bcn = bc + (size_t)n * O_SZ;
    float* nctx = reinterpret_cast<float*>(smem);               // [128][132]
    float* sdot = reinterpret_cast<float*>(smem + SD_OFF);      // [128][8]
    float* pv   = reinterpret_cast<float*>(smem + PV_OFF);      // [128]

    float dotr[4][2] = {{0.f, 0.f}, {0.f, 0.f}, {0.f, 0.f}, {0.f, 0.f}};
#pragma unroll
    for (int mt = 0; mt < 4; ++mt) {
#pragma unroll
        for (int nt = 0; nt < 4; ++nt) {
            const int colb = wn * 32 + nt * 8 + 2 * (lane & 3);
            const float b0v = bcn[colb], b1v = bcn[colb + 1];
            const float w0 = wp[colb],  w1 = wp[colb + 1];
#pragma unroll
            for (int rr = 0; rr < 2; ++rr) {
                float v0 = acc[mt][nt][2*rr]     + b0v;
                float v1 = acc[mt][nt][2*rr + 1] + b1v;
                v0 = (v0 >= 0.f) ? v0 : SLOPE * v0;
                v1 = (v1 >= 0.f) ? v1 : SLOPE * v1;
                acc[mt][nt][2*rr] = v0; acc[mt][nt][2*rr + 1] = v1;
                dotr[mt][rr] = fmaf(v0, w0, fmaf(v1, w1, dotr[mt][rr]));
            }
        }
    }
#pragma unroll
    for (int mt = 0; mt < 4; ++mt)
#pragma unroll
        for (int rr = 0; rr < 2; ++rr) {
            dotr[mt][rr] += __shfl_xor_sync(0xffffffffu, dotr[mt][rr], 1);
            dotr[mt][rr] += __shfl_xor_sync(0xffffffffu, dotr[mt][rr], 2);
        }
    if ((lane & 3) == 0) {
#pragma unroll
        for (int mt = 0; mt < 4; ++mt)
#pragma unroll
            for (int rr = 0; rr < 2; ++rr) {
                const int row = wm * 64 + mt * 16 + (lane >> 2) + 8 * rr;
                sdot[row * 8 + wn] = dotr[mt][rr];
            }
    }
    if (wn >= 4) {   // stage negative half (cols 128..255) for the blend
#pragma unroll
        for (int mt = 0; mt < 4; ++mt)
#pragma unroll
            for (int nt = 0; nt < 4; ++nt) {
                const int row = wm * 64 + mt * 16 + (lane >> 2);
                const int col = (wn - 4) * 32 + nt * 8 + 2 * (lane & 3);
                nctx[row * 132 + col]           = acc[mt][nt][0];
                nctx[row * 132 + col + 1]       = acc[mt][nt][1];
                nctx[(row + 8) * 132 + col]     = acc[mt][nt][2];
                nctx[(row + 8) * 132 + col + 1] = acc[mt][nt][3];
            }
    }
    __syncthreads();

    if (tid < 128) {
        float s = 0.f;
#pragma unroll
        for (int q = 0; q < 8; ++q) s += sdot[tid * 8 + q];
        const float p = 1.f / (1.f + expf(-(s + *bp)));
        pv[tid] = p;
        out[(size_t)B_SZ * N_C * E_SZ + (size_t)(m0 + tid) * N_C + n] = p;
    }
    __syncthreads();

    if (wn < 4) {    // blend + store c_emb
#pragma unroll
        for (int mt = 0; mt < 4; ++mt) {
#pragma unroll
            for (int rr = 0; rr < 2; ++rr) {
                const int row = wm * 64 + mt * 16 + (lane >> 2) + 8 * rr;
                const float p = pv[row];
                float* orow = out + ((size_t)(m0 + row) * N_C + n) * E_SZ;
#pragma unroll
                for (int nt = 0; nt < 4; ++nt) {
                    const int col = wn * 32 + nt * 8 + 2 * (lane & 3);
                    const float p0 = acc[mt][nt][2*rr], p1 = acc[mt][nt][2*rr + 1];
                    const float g0 = nctx[row * 132 + col];
                    const float g1 = nctx[row * 132 + col + 1];
                    *reinterpret_cast<float2*>(orow + col) =
                        make_float2(fmaf(p0 - g0, p, g0), fmaf(p1 - g1, p, g1));
                }
            }
        }
    }
}

// ---------------- launch ----------------
extern "C" void kernel_launch(void* const* d_in, const int* in_sizes, int n_in,
                              void* d_out, int out_size)
{
    const float* x  = (const float*)d_in[0];   // [2048,1024]
    const float* Wc = (const float*)d_in[1];   // [64,1024,256]
    const float* bc = (const float*)d_in[2];   // [64,256]
    const float* wp = (const float*)d_in[3];   // [256]
    const float* bp = (const float*)d_in[4];   // scalar
    float* out = (float*)d_out;

    cudaFuncSetAttribute(concept_mma_kernel,
                         cudaFuncAttributeMaxDynamicSharedMemorySize, SMEM_TOTAL);

    conv_x<<<(B_SZ * IN_F / 32) / 256, 256>>>(x);
    conv_w<<<dim3(IN_F / 32, O_SZ / 32, N_C), dim3(32, 8)>>>(Wc);
    concept_mma_kernel<<<dim3(B_SZ / TM, N_C), 512, SMEM_TOTAL>>>(bc, wp, bp, out);
}